// round 4
// baseline (speedup 1.0000x reference)
#include <cuda_runtime.h>
#include <math.h>
#include <stdint.h>

// Problem dims (fixed by the dataset)
#define T_TOK 4096     // B*L tokens
#define D_DIM 1024
#define E_EXP 8
#define F_DIM 2048
#define TWOF  4096
#define TOPK  2

// GEMM tiling
#define BM 64
#define BN 64
#define BK 16
#define SA 68          // smem row stride (floats) — kills k-aliased bank conflicts, keeps 16B alignment

// ---------------- device scratch (static; no allocations allowed) ----------------
__device__ int   g_cnt[E_EXP];
__device__ int   g_off[E_EXP];
__device__ int   g_fill[E_EXP];
__device__ int   g_exp[T_TOK * TOPK];
__device__ float g_wt [T_TOK * TOPK];
__device__ int   g_tok[T_TOK * TOPK];          // token id per global slot
__device__ int   g_slot[T_TOK * TOPK];         // (t,k) -> global slot
__device__ float g_h[(size_t)(T_TOK * TOPK + BM) * F_DIM];   // swiglu activations, padded rows
__device__ float g_y[(size_t)(T_TOK * TOPK + BM) * D_DIM];   // expert outputs, padded rows

// ---------------- init ----------------
__global__ void init_kernel() {
    int i = threadIdx.x;
    if (i < E_EXP) { g_cnt[i] = 0; g_fill[i] = 0; }
}

// ---------------- gating: one warp per token ----------------
__global__ __launch_bounds__(128) void gate_kernel(const float* __restrict__ x,
                                                   const float* __restrict__ gw) {
    int t = blockIdx.x * 4 + threadIdx.y;
    int lane = threadIdx.x;
    if (t >= T_TOK) return;
    const float* xr = x + (size_t)t * D_DIM;
    float acc[E_EXP];
#pragma unroll
    for (int e = 0; e < E_EXP; e++) acc[e] = 0.f;
    for (int d = lane; d < D_DIM; d += 32) {
        float xv = xr[d];
        const float* g = gw + (size_t)d * E_EXP;
#pragma unroll
        for (int e = 0; e < E_EXP; e++) acc[e] += xv * g[e];
    }
#pragma unroll
    for (int e = 0; e < E_EXP; e++) {
#pragma unroll
        for (int o = 16; o > 0; o >>= 1) acc[e] += __shfl_xor_sync(0xffffffffu, acc[e], o);
    }
    if (lane == 0) {
        int b0 = 0; float v0 = acc[0];
#pragma unroll
        for (int e = 1; e < E_EXP; e++) if (acc[e] > v0) { v0 = acc[e]; b0 = e; }  // strict > = earliest-index ties (JAX)
        int b1 = -1; float v1 = -1e30f;
#pragma unroll
        for (int e = 0; e < E_EXP; e++) {
            if (e != b0 && acc[e] > v1) { v1 = acc[e]; b1 = e; }
        }
        float e1v = expf(v1 - v0);
        float inv = 1.f / (1.f + e1v);
        g_exp[t * 2 + 0] = b0;  g_exp[t * 2 + 1] = b1;
        g_wt [t * 2 + 0] = inv; g_wt [t * 2 + 1] = e1v * inv;
        atomicAdd(&g_cnt[b0], 1);
        atomicAdd(&g_cnt[b1], 1);
    }
}

// ---------------- exclusive scan over 8 counts ----------------
__global__ void scan_kernel() {
    if (threadIdx.x == 0) {
        int s = 0;
        for (int e = 0; e < E_EXP; e++) { g_off[e] = s; s += g_cnt[e]; }
    }
}

// ---------------- scatter tokens into per-expert slot lists ----------------
__global__ __launch_bounds__(256) void scatter_kernel() {
    int t = blockIdx.x * blockDim.x + threadIdx.x;
    if (t >= T_TOK) return;
#pragma unroll
    for (int k = 0; k < TOPK; k++) {
        int e = g_exp[t * 2 + k];
        int p = atomicAdd(&g_fill[e], 1);
        int g = g_off[e] + p;
        g_tok[g] = t;
        g_slot[t * 2 + k] = g;
    }
}

// ---------------- GEMM1 + swiglu:  h[g, f] = swiglu(W1[e] @ x[tok])  ----------------
__global__ __launch_bounds__(256) void gemm1_kernel(const float* __restrict__ x,
                                                    const float* __restrict__ w1,
                                                    const float* __restrict__ b1) {
    const int e   = blockIdx.z;
    const int cnt = g_cnt[e];
    const int m0  = blockIdx.x * BM;
    if (m0 >= cnt) return;
    const int off = g_off[e];
    const int n0  = blockIdx.y * BN;

    __shared__ float As[BK][SA];
    __shared__ float Bs[BK][SA];
    __shared__ int   toks[BM];

    const int tid = threadIdx.x;
    if (tid < BM) toks[tid] = (m0 + tid < cnt) ? g_tok[off + m0 + tid] : g_tok[off];
    __syncthreads();

    const int r  = tid >> 2;
    const int kc = (tid & 3) << 2;
    const int tx = tid & 15;
    const int ty = tid >> 4;
    const float* wrow = w1 + ((size_t)e * TWOF + n0 + r) * D_DIM + kc;

    float acc[4][4];
#pragma unroll
    for (int i = 0; i < 4; i++)
#pragma unroll
        for (int j = 0; j < 4; j++) acc[i][j] = 0.f;

    const float* arow = x + (size_t)toks[r] * D_DIM + kc;

    for (int k0 = 0; k0 < D_DIM; k0 += BK) {
        float4 av = *(const float4*)(arow + k0);
        float4 bv = *(const float4*)(wrow + k0);
        As[kc + 0][r] = av.x; As[kc + 1][r] = av.y; As[kc + 2][r] = av.z; As[kc + 3][r] = av.w;
        Bs[kc + 0][r] = bv.x; Bs[kc + 1][r] = bv.y; Bs[kc + 2][r] = bv.z; Bs[kc + 3][r] = bv.w;
        __syncthreads();
#pragma unroll
        for (int k = 0; k < BK; k++) {
            float4 a4 = *(const float4*)&As[k][ty * 4];
            float4 b4 = *(const float4*)&Bs[k][tx * 4];
            float a_[4] = {a4.x, a4.y, a4.z, a4.w};
            float b_[4] = {b4.x, b4.y, b4.z, b4.w};
#pragma unroll
            for (int i = 0; i < 4; i++)
#pragma unroll
                for (int j = 0; j < 4; j++) acc[i][j] += a_[i] * b_[j];
        }
        __syncthreads();
    }

    // fused swiglu epilogue: columns [n0+tx*4, +4) are 2 complete (gate,val) pairs
#pragma unroll
    for (int i = 0; i < 4; i++) {
        int m = m0 + ty * 4 + i;
        if (m >= cnt) continue;
        size_t g = (size_t)(off + m);
#pragma unroll
        for (int p = 0; p < 2; p++) {
            int c = n0 + tx * 4 + p * 2;
            float gg = acc[i][p * 2 + 0] + b1[(size_t)e * TWOF + c];
            float vv = acc[i][p * 2 + 1] + b1[(size_t)e * TWOF + c + 1];
            gg = fminf(gg, 9.0f);
            vv = fminf(fmaxf(vv, -9.0f), 9.0f);
            float sg = 1.0f / (1.0f + expf(-1.702f * gg));
            g_h[g * F_DIM + (c >> 1)] = gg * sg * (vv + 1.0f);
        }
    }
}

// ---------------- GEMM2:  y[g, d] = W2[e] @ h[g]  ----------------
__global__ __launch_bounds__(256) void gemm2_kernel(const float* __restrict__ w2,
                                                    const float* __restrict__ b2) {
    const int e   = blockIdx.z;
    const int cnt = g_cnt[e];
    const int m0  = blockIdx.x * BM;
    if (m0 >= cnt) return;
    const int off = g_off[e];
    const int n0  = blockIdx.y * BN;

    __shared__ float As[BK][SA];
    __shared__ float Bs[BK][SA];

    const int tid = threadIdx.x;
    const int r  = tid >> 2;
    const int kc = (tid & 3) << 2;
    const int tx = tid & 15;
    const int ty = tid >> 4;

    const float* arow = g_h + (size_t)(off + m0 + r) * F_DIM + kc;   // padded buffer: safe past cnt
    const float* wrow = w2 + ((size_t)e * D_DIM + n0 + r) * F_DIM + kc;

    float acc[4][4];
#pragma unroll
    for (int i = 0; i < 4; i++)
#pragma unroll
        for (int j = 0; j < 4; j++) acc[i][j] = 0.f;

    for (int k0 = 0; k0 < F_DIM; k0 += BK) {
        float4 av = *(const float4*)(arow + k0);
        float4 bv = *(const float4*)(wrow + k0);
        As[kc + 0][r] = av.x; As[kc + 1][r] = av.y; As[kc + 2][r] = av.z; As[kc + 3][r] = av.w;
        Bs[kc + 0][r] = bv.x; Bs[kc + 1][r] = bv.y; Bs[kc + 2][r] = bv.z; Bs[kc + 3][r] = bv.w;
        __syncthreads();
#pragma unroll
        for (int k = 0; k < BK; k++) {
            float4 a4 = *(const float4*)&As[k][ty * 4];
            float4 b4 = *(const float4*)&Bs[k][tx * 4];
            float a_[4] = {a4.x, a4.y, a4.z, a4.w};
            float b_[4] = {b4.x, b4.y, b4.z, b4.w};
#pragma unroll
            for (int i = 0; i < 4; i++)
#pragma unroll
                for (int j = 0; j < 4; j++) acc[i][j] += a_[i] * b_[j];
        }
        __syncthreads();
    }

#pragma unroll
    for (int i = 0; i < 4; i++) {
        int m = m0 + ty * 4 + i;
        if (m >= cnt) continue;
        size_t g = (size_t)(off + m);
#pragma unroll
        for (int j = 0; j < 4; j++) {
            int c = n0 + tx * 4 + j;
            g_y[g * D_DIM + c] = acc[i][j] + b2[(size_t)e * D_DIM + c];
        }
    }
}

// ---------------- combine: out[t] = w0*y[slot0] + w1*y[slot1] ----------------
__global__ __launch_bounds__(256) void combine_kernel(float* __restrict__ out) {
    int t = blockIdx.x;
    int d = threadIdx.x * 4;
    int s0 = g_slot[t * 2 + 0], s1 = g_slot[t * 2 + 1];
    float w0 = g_wt[t * 2 + 0], w1 = g_wt[t * 2 + 1];
    float4 a = *(const float4*)&g_y[(size_t)s0 * D_DIM + d];
    float4 b = *(const float4*)&g_y[(size_t)s1 * D_DIM + d];
    float4 o;
    o.x = w0 * a.x + w1 * b.x;
    o.y = w0 * a.y + w1 * b.y;
    o.z = w0 * a.z + w1 * b.z;
    o.w = w0 * a.w + w1 * b.w;
    *(float4*)&out[(size_t)t * D_DIM + d] = o;
}

// ---------------- launch ----------------
extern "C" void kernel_launch(void* const* d_in, const int* in_sizes, int n_in,
                              void* d_out, int out_size) {
    const float* x   = (const float*)d_in[0];   // (B,L,D)
    const float* gw  = (const float*)d_in[1];   // (D,E)
    const float* w1  = (const float*)d_in[2];   // (E,2F,D)
    const float* b1  = (const float*)d_in[3];   // (E,2F)
    const float* w2  = (const float*)d_in[4];   // (E,D,F)
    const float* b2  = (const float*)d_in[5];   // (E,D)
    float* out = (float*)d_out;

    init_kernel<<<1, 32>>>();
    gate_kernel<<<T_TOK / 4, dim3(32, 4)>>>(x, gw);
    scan_kernel<<<1, 32>>>();
    scatter_kernel<<<T_TOK / 256, 256>>>();
    gemm1_kernel<<<dim3(T_TOK / BM, TWOF / BN, E_EXP), 256>>>(x, w1, b1);
    gemm2_kernel<<<dim3(T_TOK / BM, D_DIM / BN, E_EXP), 256>>>(w2, b2);
    combine_kernel<<<T_TOK, 256>>>(out);
}

// round 10
// speedup vs baseline: 2.2861x; 2.2861x over previous
#include <cuda_runtime.h>
#include <math.h>
#include <stdint.h>

// Problem dims (fixed by the dataset)
#define T_TOK 4096     // B*L tokens
#define D_DIM 1024
#define E_EXP 8
#define F_DIM 2048
#define TWOF  4096
#define TOPK  2

// GEMM tiling: 128x128 block tile, BK=32 tf32 (=128B row, SW128)
#define GBM 128
#define GBN 128
#define GBK 32
#define TILE_BYTES 16384                 // 128 rows * 128 B
#define BUF_BYTES  (2 * TILE_BYTES)      // A + B per stage
#define SMEM_REQ   (2 * BUF_BYTES + 1024 /*align*/ + 1024 /*toks etc*/)

// ---------------- device scratch (static; no allocations allowed) ----------------
__device__ int   g_cnt[E_EXP];
__device__ int   g_off[E_EXP];
__device__ int   g_fill[E_EXP];
__device__ int   g_exp[T_TOK * TOPK];
__device__ float g_wt [T_TOK * TOPK];
__device__ int   g_tok[T_TOK * TOPK];
__device__ int   g_slot[T_TOK * TOPK];
__device__ float g_xr [T_TOK * D_DIM];                        // tf32-rounded x
__device__ float g_w1r[(size_t)E_EXP * TWOF * D_DIM];         // tf32-rounded W1
__device__ float g_w2r[(size_t)E_EXP * D_DIM * F_DIM];        // tf32-rounded W2
__device__ float g_h[(size_t)(T_TOK * TOPK + GBM) * F_DIM];   // swiglu acts (tf32-rounded), padded
__device__ float g_y[(size_t)(T_TOK * TOPK + GBM) * D_DIM];   // expert outputs, padded

// ---------------- helpers ----------------
__device__ __forceinline__ uint32_t smem_u32(const void* p) {
    uint32_t a;
    asm("{ .reg .u64 t; cvta.to.shared.u64 t, %1; cvt.u32.u64 %0, t; }" : "=r"(a) : "l"(p));
    return a;
}
__device__ __forceinline__ float tf32r(float x) {
    uint32_t u;
    asm("cvt.rna.tf32.f32 %0, %1;" : "=r"(u) : "f"(x));
    return __uint_as_float(u);
}
#define SW128(b) ((b) ^ (((b) >> 3) & 0x70))

#define CP_ASYNC16(dst, src) \
    asm volatile("cp.async.cg.shared.global [%0], [%1], 16;" :: "r"(dst), "l"(src))
#define CP_COMMIT() asm volatile("cp.async.commit_group;")
#define CP_WAIT0()  asm volatile("cp.async.wait_group 0;")

#define LDSM_X4(r, addr) \
    asm volatile("ldmatrix.sync.aligned.m8n8.x4.shared.b16 {%0,%1,%2,%3}, [%4];" \
        : "=r"((r)[0]), "=r"((r)[1]), "=r"((r)[2]), "=r"((r)[3]) : "r"(addr))

#define MMA_TF32(c, a, bb0, bb1) \
    asm volatile("mma.sync.aligned.m16n8k8.row.col.f32.tf32.tf32.f32 " \
        "{%0,%1,%2,%3}, {%4,%5,%6,%7}, {%8,%9}, {%0,%1,%2,%3};" \
        : "+f"((c)[0]), "+f"((c)[1]), "+f"((c)[2]), "+f"((c)[3]) \
        : "r"((a)[0]), "r"((a)[1]), "r"((a)[2]), "r"((a)[3]), "r"(bb0), "r"(bb1))

// ---------------- init ----------------
__global__ void init_kernel() {
    int i = threadIdx.x;
    if (i < E_EXP) { g_cnt[i] = 0; g_fill[i] = 0; }
}

// ---------------- tf32 rounding pre-pass (x, W1, W2) ----------------
#define N4_X  (T_TOK * D_DIM / 4)
#define N4_W1 ((int)((size_t)E_EXP * TWOF * D_DIM / 4))
#define N4_W2 ((int)((size_t)E_EXP * D_DIM * F_DIM / 4))
#define N4_ALL (N4_X + N4_W1 + N4_W2)

__global__ __launch_bounds__(256) void round_kernel(const float4* __restrict__ x,
                                                    const float4* __restrict__ w1,
                                                    const float4* __restrict__ w2) {
    int i = blockIdx.x * 256 + threadIdx.x;
    if (i >= N4_ALL) return;
    const float4* s; float4* d;
    if (i < N4_W1)               { s = w1 + i;                 d = (float4*)g_w1r + i; }
    else if (i < N4_W1 + N4_W2)  { int j = i - N4_W1;          s = w2 + j; d = (float4*)g_w2r + j; }
    else                         { int j = i - N4_W1 - N4_W2;  s = x + j;  d = (float4*)g_xr + j; }
    float4 v = *s;
    v.x = tf32r(v.x); v.y = tf32r(v.y); v.z = tf32r(v.z); v.w = tf32r(v.w);
    *d = v;
}

// ---------------- gating: one warp per token ----------------
__global__ __launch_bounds__(128) void gate_kernel(const float* __restrict__ x,
                                                   const float* __restrict__ gw) {
    int t = blockIdx.x * 4 + threadIdx.y;
    int lane = threadIdx.x;
    if (t >= T_TOK) return;
    const float* xr = x + (size_t)t * D_DIM;
    float acc[E_EXP];
#pragma unroll
    for (int e = 0; e < E_EXP; e++) acc[e] = 0.f;
    for (int d = lane; d < D_DIM; d += 32) {
        float xv = xr[d];
        const float* g = gw + (size_t)d * E_EXP;
#pragma unroll
        for (int e = 0; e < E_EXP; e++) acc[e] += xv * g[e];
    }
#pragma unroll
    for (int e = 0; e < E_EXP; e++) {
#pragma unroll
        for (int o = 16; o > 0; o >>= 1) acc[e] += __shfl_xor_sync(0xffffffffu, acc[e], o);
    }
    if (lane == 0) {
        int b0 = 0; float v0 = acc[0];
#pragma unroll
        for (int e = 1; e < E_EXP; e++) if (acc[e] > v0) { v0 = acc[e]; b0 = e; }
        int b1 = -1; float v1 = -1e30f;
#pragma unroll
        for (int e = 0; e < E_EXP; e++) if (e != b0 && acc[e] > v1) { v1 = acc[e]; b1 = e; }
        float e1v = expf(v1 - v0);
        float inv = 1.f / (1.f + e1v);
        g_exp[t * 2 + 0] = b0;  g_exp[t * 2 + 1] = b1;
        g_wt [t * 2 + 0] = inv; g_wt [t * 2 + 1] = e1v * inv;
        atomicAdd(&g_cnt[b0], 1);
        atomicAdd(&g_cnt[b1], 1);
    }
}

__global__ void scan_kernel() {
    if (threadIdx.x == 0) {
        int s = 0;
        for (int e = 0; e < E_EXP; e++) { g_off[e] = s; s += g_cnt[e]; }
    }
}

__global__ __launch_bounds__(256) void scatter_kernel() {
    int t = blockIdx.x * blockDim.x + threadIdx.x;
    if (t >= T_TOK) return;
#pragma unroll
    for (int k = 0; k < TOPK; k++) {
        int e = g_exp[t * 2 + k];
        int p = atomicAdd(&g_fill[e], 1);
        int g = g_off[e] + p;
        g_tok[g] = t;
        g_slot[t * 2 + k] = g;
    }
}

// ---------------- tf32 mma.sync grouped GEMM ----------------
// WHICH=1: h = swiglu(x_gathered @ W1^T + b1)   (K=1024, N=4096)
// WHICH=2: y = h @ W2^T + b2                    (K=2048, N=1024)
template <int WHICH>
__global__ __launch_bounds__(256, 2) void moe_gemm_kernel(const float* __restrict__ bias) {
    constexpr int KT = (WHICH == 1) ? D_DIM : F_DIM;
    constexpr int NT = (WHICH == 1) ? TWOF  : D_DIM;
    constexpr int NK = KT / GBK;

    const int e   = blockIdx.z;
    const int cnt = g_cnt[e];
    const int m0  = blockIdx.x * GBM;
    if (m0 >= cnt) return;
    const int off = g_off[e];
    const int n0  = blockIdx.y * GBN;
    const int tid = threadIdx.x;
    const int lane = tid & 31;
    const int wid  = tid >> 5;
    const int warp_m = wid & 1;   // 2 x 64 rows
    const int warp_n = wid >> 1;  // 4 x 32 cols

    extern __shared__ char smem_raw[];
    const uint32_t sb_raw = smem_u32(smem_raw);
    const uint32_t sb     = (sb_raw + 1023) & ~1023u;   // 1024-aligned tile base
    int* toks = (int*)(smem_raw + (sb - sb_raw) + 2 * BUF_BYTES);

    if (WHICH == 1) {
        if (tid < GBM) toks[tid] = (m0 + tid < cnt) ? g_tok[off + m0 + tid] : g_tok[off];
        __syncthreads();
    }

    // ---- cp.async mapping: thread -> (row = tid&127, 64B half = tid>>7) ----
    const int lr   = tid & 127;
    const int half = tid >> 7;
    const float* arow;
    if (WHICH == 1) arow = g_xr + (size_t)toks[lr] * D_DIM + half * 16;
    else            arow = g_h  + (size_t)(off + m0 + lr) * F_DIM + half * 16;
    const float* brow = ((WHICH == 1) ? g_w1r : g_w2r)
                        + ((size_t)e * NT + n0 + lr) * KT + half * 16;
    uint32_t wsw[4];
#pragma unroll
    for (int s = 0; s < 4; s++) wsw[s] = SW128((uint32_t)(lr * 128 + half * 64 + s * 16));

#define LOAD_CHUNK(ci, buf)                                          \
    {                                                                \
        uint32_t ab = sb + (buf) * BUF_BYTES;                        \
        uint32_t bb = ab + TILE_BYTES;                               \
        const float* ap = arow + (ci) * GBK;                         \
        const float* bp = brow + (ci) * GBK;                         \
        _Pragma("unroll")                                            \
        for (int s = 0; s < 4; s++) {                                \
            CP_ASYNC16(ab + wsw[s], ap + s * 4);                     \
            CP_ASYNC16(bb + wsw[s], bp + s * 4);                     \
        }                                                            \
        CP_COMMIT();                                                 \
    }

    // ---- ldmatrix per-lane address components ----
    const int q = lane >> 3, r8 = lane & 7;
    // A: mat0=(row+0,b0) mat1=(row+8,b0) mat2=(row+0,b16) mat3=(row+8,b16)
    const uint32_t aoff0 = (uint32_t)((warp_m * 64 + r8 + ((q & 1) ? 8 : 0)) * 128 + ((q & 2) ? 16 : 0));
    // B: mat0=(n+0,b0) mat1=(n+0,b16) mat2=(n+8,b0) mat3=(n+8,b16)
    const uint32_t boff0 = (uint32_t)((warp_n * 32 + r8 + ((q & 2) ? 8 : 0)) * 128 + ((q & 1) ? 16 : 0));

    float c[4][4][4];
#pragma unroll
    for (int mt = 0; mt < 4; mt++)
#pragma unroll
        for (int nt = 0; nt < 4; nt++)
#pragma unroll
            for (int v = 0; v < 4; v++) c[mt][nt][v] = 0.f;

    LOAD_CHUNK(0, 0);

    for (int i = 0; i < NK; i++) {
        CP_WAIT0();
        __syncthreads();
        if (i + 1 < NK) LOAD_CHUNK(i + 1, (i + 1) & 1);

        const uint32_t ab = sb + (i & 1) * BUF_BYTES;
        const uint32_t bb = ab + TILE_BYTES;
#pragma unroll
        for (int s = 0; s < 4; s++) {
            uint32_t af[4][4];
#pragma unroll
            for (int mt = 0; mt < 4; mt++)
                LDSM_X4(af[mt], ab + SW128(aoff0 + (uint32_t)(mt * 2048 + s * 32)));
            uint32_t bf[2][4];
#pragma unroll
            for (int jp = 0; jp < 2; jp++)
                LDSM_X4(bf[jp], bb + SW128(boff0 + (uint32_t)(jp * 2048 + s * 32)));
#pragma unroll
            for (int mt = 0; mt < 4; mt++)
#pragma unroll
                for (int nt = 0; nt < 4; nt++)
                    MMA_TF32(c[mt][nt], af[mt], bf[nt >> 1][(nt & 1) * 2],
                             bf[nt >> 1][(nt & 1) * 2 + 1]);
        }
    }
#undef LOAD_CHUNK

    // ---- epilogue: C frag (mt,nt): regs {0,1}=(row g, cols 2t,2t+1), {2,3}=(row g+8) ----
    const int g  = lane >> 2, t4 = lane & 3;
    const float* bp = bias + (size_t)e * NT;
#pragma unroll
    for (int mt = 0; mt < 4; mt++) {
#pragma unroll
        for (int part = 0; part < 2; part++) {
            int m = m0 + warp_m * 64 + mt * 16 + g + part * 8;
            if (m >= cnt) continue;
            size_t gs = (size_t)(off + m);
#pragma unroll
            for (int nt = 0; nt < 4; nt++) {
                int nc = n0 + warp_n * 32 + nt * 8 + 2 * t4;
                float v0 = c[mt][nt][part * 2 + 0] + bp[nc];
                float v1 = c[mt][nt][part * 2 + 1] + bp[nc + 1];
                if (WHICH == 1) {
                    float gg = fminf(v0, 9.0f);
                    float vv = fminf(fmaxf(v1, -9.0f), 9.0f);
                    float sg = 1.0f / (1.0f + expf(-1.702f * gg));
                    g_h[gs * F_DIM + (nc >> 1)] = tf32r(gg * sg * (vv + 1.0f));
                } else {
                    g_y[gs * D_DIM + nc]     = v0;
                    g_y[gs * D_DIM + nc + 1] = v1;
                }
            }
        }
    }
}

// ---------------- combine: out[t] = w0*y[slot0] + w1*y[slot1] ----------------
__global__ __launch_bounds__(256) void combine_kernel(float* __restrict__ out) {
    int t = blockIdx.x;
    int d = threadIdx.x * 4;
    int s0 = g_slot[t * 2 + 0], s1 = g_slot[t * 2 + 1];
    float w0 = g_wt[t * 2 + 0], w1 = g_wt[t * 2 + 1];
    float4 a = *(const float4*)&g_y[(size_t)s0 * D_DIM + d];
    float4 b = *(const float4*)&g_y[(size_t)s1 * D_DIM + d];
    float4 o;
    o.x = w0 * a.x + w1 * b.x;
    o.y = w0 * a.y + w1 * b.y;
    o.z = w0 * a.z + w1 * b.z;
    o.w = w0 * a.w + w1 * b.w;
    *(float4*)&out[(size_t)t * D_DIM + d] = o;
}

// ---------------- launch ----------------
extern "C" void kernel_launch(void* const* d_in, const int* in_sizes, int n_in,
                              void* d_out, int out_size) {
    const float* x   = (const float*)d_in[0];   // (B,L,D)
    const float* gw  = (const float*)d_in[1];   // (D,E)
    const float* w1  = (const float*)d_in[2];   // (E,2F,D)
    const float* b1  = (const float*)d_in[3];   // (E,2F)
    const float* w2  = (const float*)d_in[4];   // (E,D,F)
    const float* b2  = (const float*)d_in[5];   // (E,D)
    float* out = (float*)d_out;

    cudaFuncSetAttribute(moe_gemm_kernel<1>, cudaFuncAttributeMaxDynamicSharedMemorySize, SMEM_REQ);
    cudaFuncSetAttribute(moe_gemm_kernel<2>, cudaFuncAttributeMaxDynamicSharedMemorySize, SMEM_REQ);

    init_kernel<<<1, 32>>>();
    round_kernel<<<(N4_ALL + 255) / 256, 256>>>((const float4*)x, (const float4*)w1,
                                                (const float4*)w2);
    gate_kernel<<<T_TOK / 4, dim3(32, 4)>>>(x, gw);
    scan_kernel<<<1, 32>>>();
    scatter_kernel<<<T_TOK / 256, 256>>>();
    moe_gemm_kernel<1><<<dim3(T_TOK * TOPK / GBM, TWOF / GBN, E_EXP), 256, SMEM_REQ>>>(b1);
    moe_gemm_kernel<2><<<dim3(T_TOK * TOPK / GBM, D_DIM / GBN, E_EXP), 256, SMEM_REQ>>>(b2);
    combine_kernel<<<T_TOK, 256>>>(out);
}

// round 12
// speedup vs baseline: 2.3521x; 1.0289x over previous
#include <cuda_runtime.h>
#include <math.h>
#include <stdint.h>

// Problem dims (fixed by the dataset)
#define T_TOK 4096     // B*L tokens
#define D_DIM 1024
#define E_EXP 8
#define F_DIM 2048
#define TWOF  4096
#define TOPK  2

// GEMM tiling: 128x256 CTA tile, 64x64 warp tile (8 warps, 2x4), BK=32 tf32 (=128B SW128 row)
#define GBM 128
#define GBN 256
#define GBK 32
#define A_BYTES 16384                    // 128 rows * 128 B
#define B_BYTES 32768                    // 256 rows * 128 B
#define STG_BYTES (A_BYTES + B_BYTES)    // 48 KB per stage
#define NSTAGE 3
#define SMEM_REQ (NSTAGE * STG_BYTES + 1024 /*align*/ + 1024 /*toks*/)

// ---------------- device scratch (static; no allocations allowed) ----------------
__device__ int   g_cnt[E_EXP];
__device__ int   g_off[E_EXP];
__device__ int   g_fill[E_EXP];
__device__ int   g_exp[T_TOK * TOPK];
__device__ float g_wt [T_TOK * TOPK];
__device__ int   g_tok[T_TOK * TOPK];
__device__ int   g_slot[T_TOK * TOPK];
__device__ float g_xr [T_TOK * D_DIM];                        // tf32-rounded x
__device__ float g_w1r[(size_t)E_EXP * TWOF * D_DIM];         // tf32-rounded W1
__device__ float g_w2r[(size_t)E_EXP * D_DIM * F_DIM];        // tf32-rounded W2
__device__ float g_h[(size_t)(T_TOK * TOPK + GBM) * F_DIM];   // swiglu acts (tf32-rounded), padded
__device__ float g_y[(size_t)(T_TOK * TOPK + GBM) * D_DIM];   // expert outputs, padded

// ---------------- helpers ----------------
__device__ __forceinline__ uint32_t smem_u32(const void* p) {
    uint32_t a;
    asm("{ .reg .u64 t; cvta.to.shared.u64 t, %1; cvt.u32.u64 %0, t; }" : "=r"(a) : "l"(p));
    return a;
}
__device__ __forceinline__ float tf32r(float x) {
    uint32_t u;
    asm("cvt.rna.tf32.f32 %0, %1;" : "=r"(u) : "f"(x));
    return __uint_as_float(u);
}
#define SW128(b) ((b) ^ (((b) >> 3) & 0x70))

#define CP_ASYNC16(dst, src) \
    asm volatile("cp.async.cg.shared.global [%0], [%1], 16;" :: "r"(dst), "l"(src))
#define CP_COMMIT() asm volatile("cp.async.commit_group;")
#define CP_WAIT1()  asm volatile("cp.async.wait_group 1;")
#define CP_WAIT0()  asm volatile("cp.async.wait_group 0;")

#define LDSM_X4(r, addr) \
    asm volatile("ldmatrix.sync.aligned.m8n8.x4.shared.b16 {%0,%1,%2,%3}, [%4];" \
        : "=r"((r)[0]), "=r"((r)[1]), "=r"((r)[2]), "=r"((r)[3]) : "r"(addr))

#define MMA_TF32(c, a, bb0, bb1) \
    asm volatile("mma.sync.aligned.m16n8k8.row.col.f32.tf32.tf32.f32 " \
        "{%0,%1,%2,%3}, {%4,%5,%6,%7}, {%8,%9}, {%0,%1,%2,%3};" \
        : "+f"((c)[0]), "+f"((c)[1]), "+f"((c)[2]), "+f"((c)[3]) \
        : "r"((a)[0]), "r"((a)[1]), "r"((a)[2]), "r"((a)[3]), "r"(bb0), "r"(bb1))

// ---------------- init ----------------
__global__ void init_kernel() {
    int i = threadIdx.x;
    if (i < E_EXP) { g_cnt[i] = 0; g_fill[i] = 0; }
}

// ---------------- tf32 rounding pre-pass (x, W1, W2) ----------------
#define N4_X  (T_TOK * D_DIM / 4)
#define N4_W1 ((int)((size_t)E_EXP * TWOF * D_DIM / 4))
#define N4_W2 ((int)((size_t)E_EXP * D_DIM * F_DIM / 4))
#define N4_ALL (N4_X + N4_W1 + N4_W2)

__global__ __launch_bounds__(256) void round_kernel(const float4* __restrict__ x,
                                                    const float4* __restrict__ w1,
                                                    const float4* __restrict__ w2) {
    int i = blockIdx.x * 256 + threadIdx.x;
    if (i >= N4_ALL) return;
    const float4* s; float4* d;
    if (i < N4_W1)               { s = w1 + i;                 d = (float4*)g_w1r + i; }
    else if (i < N4_W1 + N4_W2)  { int j = i - N4_W1;          s = w2 + j; d = (float4*)g_w2r + j; }
    else                         { int j = i - N4_W1 - N4_W2;  s = x + j;  d = (float4*)g_xr + j; }
    float4 v = *s;
    v.x = tf32r(v.x); v.y = tf32r(v.y); v.z = tf32r(v.z); v.w = tf32r(v.w);
    *d = v;
}

// ---------------- gating: one warp per token ----------------
__global__ __launch_bounds__(128) void gate_kernel(const float* __restrict__ x,
                                                   const float* __restrict__ gw) {
    int t = blockIdx.x * 4 + threadIdx.y;
    int lane = threadIdx.x;
    if (t >= T_TOK) return;
    const float* xr = x + (size_t)t * D_DIM;
    float acc[E_EXP];
#pragma unroll
    for (int e = 0; e < E_EXP; e++) acc[e] = 0.f;
    for (int d = lane; d < D_DIM; d += 32) {
        float xv = xr[d];
        const float* g = gw + (size_t)d * E_EXP;
#pragma unroll
        for (int e = 0; e < E_EXP; e++) acc[e] += xv * g[e];
    }
#pragma unroll
    for (int e = 0; e < E_EXP; e++) {
#pragma unroll
        for (int o = 16; o > 0; o >>= 1) acc[e] += __shfl_xor_sync(0xffffffffu, acc[e], o);
    }
    if (lane == 0) {
        int b0 = 0; float v0 = acc[0];
#pragma unroll
        for (int e = 1; e < E_EXP; e++) if (acc[e] > v0) { v0 = acc[e]; b0 = e; }
        int b1 = -1; float v1 = -1e30f;
#pragma unroll
        for (int e = 0; e < E_EXP; e++) if (e != b0 && acc[e] > v1) { v1 = acc[e]; b1 = e; }
        float e1v = expf(v1 - v0);
        float inv = 1.f / (1.f + e1v);
        g_exp[t * 2 + 0] = b0;  g_exp[t * 2 + 1] = b1;
        g_wt [t * 2 + 0] = inv; g_wt [t * 2 + 1] = e1v * inv;
        atomicAdd(&g_cnt[b0], 1);
        atomicAdd(&g_cnt[b1], 1);
    }
}

__global__ void scan_kernel() {
    if (threadIdx.x == 0) {
        int s = 0;
        for (int e = 0; e < E_EXP; e++) { g_off[e] = s; s += g_cnt[e]; }
    }
}

__global__ __launch_bounds__(256) void scatter_kernel() {
    int t = blockIdx.x * blockDim.x + threadIdx.x;
    if (t >= T_TOK) return;
#pragma unroll
    for (int k = 0; k < TOPK; k++) {
        int e = g_exp[t * 2 + k];
        int p = atomicAdd(&g_fill[e], 1);
        int g = g_off[e] + p;
        g_tok[g] = t;
        g_slot[t * 2 + k] = g;
    }
}

// ---------------- tf32 mma.sync grouped GEMM ----------------
// WHICH=1: h = swiglu(x_gathered @ W1^T + b1)   (K=1024, N=4096)
// WHICH=2: y = h @ W2^T + b2                    (K=2048, N=1024)
template <int WHICH>
__global__ __launch_bounds__(256, 1) void moe_gemm_kernel(const float* __restrict__ bias) {
    constexpr int KT = (WHICH == 1) ? D_DIM : F_DIM;
    constexpr int NT = (WHICH == 1) ? TWOF  : D_DIM;
    constexpr int NK = KT / GBK;

    const int e   = blockIdx.z;
    const int cnt = g_cnt[e];
    const int m0  = blockIdx.x * GBM;
    if (m0 >= cnt) return;
    const int off = g_off[e];
    const int n0  = blockIdx.y * GBN;
    const int tid = threadIdx.x;
    const int lane = tid & 31;
    const int wid  = tid >> 5;
    const int warp_m = wid & 1;   // 2 x 64 rows
    const int warp_n = wid >> 1;  // 4 x 64 cols

    extern __shared__ char smem_raw[];
    const uint32_t sb_raw = smem_u32(smem_raw);
    const uint32_t sb     = (sb_raw + 1023) & ~1023u;   // 1024-aligned tile base
    int* toks = (int*)(smem_raw + (sb - sb_raw) + NSTAGE * STG_BYTES);

    if (WHICH == 1) {
        if (tid < GBM) toks[tid] = (m0 + tid < cnt) ? g_tok[off + m0 + tid] : g_tok[off];
        __syncthreads();
    }

    // ---- cp.async mapping ----
    // A: thread -> (row = tid&127, 64B half = tid>>7): 4 x 16B
    // B: thread -> row tid (0..255): 8 x 16B
    const int lr   = tid & 127;
    const int half = tid >> 7;
    const float* arow;
    if (WHICH == 1) arow = g_xr + (size_t)toks[lr] * D_DIM + half * 16;
    else            arow = g_h  + (size_t)(off + m0 + lr) * F_DIM + half * 16;  // padded: safe past cnt
    const float* brow = ((WHICH == 1) ? g_w1r : g_w2r)
                        + ((size_t)e * NT + n0 + tid) * KT;
    uint32_t aswz[4], bswz[8];
#pragma unroll
    for (int s = 0; s < 4; s++) aswz[s] = SW128((uint32_t)(lr * 128 + half * 64 + s * 16));
#pragma unroll
    for (int s = 0; s < 8; s++) bswz[s] = SW128((uint32_t)(tid * 128 + s * 16));

#define LOAD_CHUNK(ci, buf)                                          \
    {                                                                \
        uint32_t ab = sb + (buf) * STG_BYTES;                        \
        uint32_t bb = ab + A_BYTES;                                  \
        const float* ap = arow + (ci) * GBK;                         \
        const float* bp = brow + (ci) * GBK;                         \
        _Pragma("unroll")                                            \
        for (int s = 0; s < 4; s++) CP_ASYNC16(ab + aswz[s], ap + s * 4); \
        _Pragma("unroll")                                            \
        for (int s = 0; s < 8; s++) CP_ASYNC16(bb + bswz[s], bp + s * 4); \
        CP_COMMIT();                                                 \
    }

    // ---- ldmatrix per-lane address components ----
    const int q = lane >> 3, r8 = lane & 7;
    // A: mat0=(row+0,b0) mat1=(row+8,b0) mat2=(row+0,b16) mat3=(row+8,b16)
    const uint32_t aoff0 = (uint32_t)((warp_m * 64 + r8 + ((q & 1) ? 8 : 0)) * 128 + ((q & 2) ? 16 : 0));
    // B: mat0=(n+0,b0) mat1=(n+0,b16) mat2=(n+8,b0) mat3=(n+8,b16)
    const uint32_t boff0 = (uint32_t)((warp_n * 64 + r8 + ((q & 2) ? 8 : 0)) * 128 + ((q & 1) ? 16 : 0));

    float c[4][8][4];
#pragma unroll
    for (int mt = 0; mt < 4; mt++)
#pragma unroll
        for (int nt = 0; nt < 8; nt++)
#pragma unroll
            for (int v = 0; v < 4; v++) c[mt][nt][v] = 0.f;

    LOAD_CHUNK(0, 0);
    LOAD_CHUNK(1, 1);

    int stg = 2;                 // stage receiving the next prefetch
    for (int i = 0; i < NK; i++) {
        if (i + 2 < NK) { CP_WAIT1(); } else { CP_WAIT0(); }
        __syncthreads();
        if (i + 2 < NK) {
            LOAD_CHUNK(i + 2, stg);
            stg = (stg == NSTAGE - 1) ? 0 : stg + 1;
        }

        const uint32_t ab = sb + (i % NSTAGE) * STG_BYTES;
        const uint32_t bb = ab + A_BYTES;
#pragma unroll
        for (int s = 0; s < 4; s++) {
            uint32_t af[4][4];
#pragma unroll
            for (int mt = 0; mt < 4; mt++)
                LDSM_X4(af[mt], ab + SW128(aoff0 + (uint32_t)(mt * 2048 + s * 32)));
            uint32_t bf[4][4];
#pragma unroll
            for (int jp = 0; jp < 4; jp++)
                LDSM_X4(bf[jp], bb + SW128(boff0 + (uint32_t)(jp * 2048 + s * 32)));
#pragma unroll
            for (int mt = 0; mt < 4; mt++)
#pragma unroll
                for (int nt = 0; nt < 8; nt++)
                    MMA_TF32(c[mt][nt], af[mt], bf[nt >> 1][(nt & 1) * 2],
                             bf[nt >> 1][(nt & 1) * 2 + 1]);
        }
    }
#undef LOAD_CHUNK

    // ---- epilogue: C frag (mt,nt): regs {0,1}=(row g, cols 2t,2t+1), {2,3}=(row g+8) ----
    const int g  = lane >> 2, t4 = lane & 3;
    const float* bp = bias + (size_t)e * NT;
#pragma unroll
    for (int mt = 0; mt < 4; mt++) {
#pragma unroll
        for (int part = 0; part < 2; part++) {
            int m = m0 + warp_m * 64 + mt * 16 + g + part * 8;
            if (m >= cnt) continue;
            size_t gs = (size_t)(off + m);
#pragma unroll
            for (int nt = 0; nt < 8; nt++) {
                int nc = n0 + warp_n * 64 + nt * 8 + 2 * t4;
                float v0 = c[mt][nt][part * 2 + 0] + bp[nc];
                float v1 = c[mt][nt][part * 2 + 1] + bp[nc + 1];
                if (WHICH == 1) {
                    float gg = fminf(v0, 9.0f);
                    float vv = fminf(fmaxf(v1, -9.0f), 9.0f);
                    float sg = 1.0f / (1.0f + expf(-1.702f * gg));
                    g_h[gs * F_DIM + (nc >> 1)] = tf32r(gg * sg * (vv + 1.0f));
                } else {
                    g_y[gs * D_DIM + nc]     = v0;
                    g_y[gs * D_DIM + nc + 1] = v1;
                }
            }
        }
    }
}

// ---------------- combine: out[t] = w0*y[slot0] + w1*y[slot1] ----------------
__global__ __launch_bounds__(256) void combine_kernel(float* __restrict__ out) {
    int t = blockIdx.x;
    int d = threadIdx.x * 4;
    int s0 = g_slot[t * 2 + 0], s1 = g_slot[t * 2 + 1];
    float w0 = g_wt[t * 2 + 0], w1 = g_wt[t * 2 + 1];
    float4 a = *(const float4*)&g_y[(size_t)s0 * D_DIM + d];
    float4 b = *(const float4*)&g_y[(size_t)s1 * D_DIM + d];
    float4 o;
    o.x = w0 * a.x + w1 * b.x;
    o.y = w0 * a.y + w1 * b.y;
    o.z = w0 * a.z + w1 * b.z;
    o.w = w0 * a.w + w1 * b.w;
    *(float4*)&out[(size_t)t * D_DIM + d] = o;
}

// ---------------- launch ----------------
extern "C" void kernel_launch(void* const* d_in, const int* in_sizes, int n_in,
                              void* d_out, int out_size) {
    const float* x   = (const float*)d_in[0];   // (B,L,D)
    const float* gw  = (const float*)d_in[1];   // (D,E)
    const float* w1  = (const float*)d_in[2];   // (E,2F,D)
    const float* b1  = (const float*)d_in[3];   // (E,2F)
    const float* w2  = (const float*)d_in[4];   // (E,D,F)
    const float* b2  = (const float*)d_in[5];   // (E,D)
    float* out = (float*)d_out;

    cudaFuncSetAttribute(moe_gemm_kernel<1>, cudaFuncAttributeMaxDynamicSharedMemorySize, SMEM_REQ);
    cudaFuncSetAttribute(moe_gemm_kernel<2>, cudaFuncAttributeMaxDynamicSharedMemorySize, SMEM_REQ);

    init_kernel<<<1, 32>>>();
    round_kernel<<<(N4_ALL + 255) / 256, 256>>>((const float4*)x, (const float4*)w1,
                                                (const float4*)w2);
    gate_kernel<<<T_TOK / 4, dim3(32, 4)>>>(x, gw);
    scan_kernel<<<1, 32>>>();
    scatter_kernel<<<T_TOK / 256, 256>>>();
    moe_gemm_kernel<1><<<dim3(T_TOK * TOPK / GBM, TWOF / GBN, E_EXP), 256, SMEM_REQ>>>(b1);
    moe_gemm_kernel<2><<<dim3(T_TOK * TOPK / GBM, D_DIM / GBN, E_EXP), 256, SMEM_REQ>>>(b2);
    combine_kernel<<<T_TOK, 256>>>(out);
}